// round 14
// baseline (speedup 1.0000x reference)
#include <cuda_runtime.h>
#include <cuda_fp16.h>
#include <math.h>

// ---------------- Problem constants ----------------
#define S_LEN 2048
#define D_MOD 768
#define N_HEADS 12
#define HDIM 64
#define QT 64
#define KW 192

// ---------------- fp16 GEMM constants ----------------
#define GK 768
#define NCHUNK 12          // GK / 64
#define CHUNK_K 64
#define GSTAGES 4

// ---------------- Scratch (no cudaMalloc allowed) ----------------
__device__ __align__(1024) __half g_Qh[S_LEN * D_MOD];
__device__ __align__(1024) __half g_Kh[S_LEN * D_MOD];
__device__ __align__(1024) __half g_Vh[S_LEN * D_MOD];
__device__ __align__(1024) __half g_Ch[S_LEN * D_MOD];
__device__ __align__(1024) __half g_Ah[3][S_LEN * D_MOD];   // fp16 activations
__device__ __align__(1024) __half g_Wh[4][D_MOD * D_MOD];   // fp16 weights [k][n]

// ---------------- PTX helpers (base sm_103-safe: sm_80 era) ----------------
__device__ __forceinline__ unsigned smem_u32(const void* p) {
    unsigned a;
    asm("{ .reg .u64 t; cvta.to.shared.u64 t, %1; cvt.u32.u64 %0, t; }"
        : "=r"(a) : "l"(p));
    return a;
}
__device__ __forceinline__ void cp_async16(unsigned saddr, const void* gptr) {
    asm volatile("cp.async.cg.shared.global [%0], [%1], 16;"
                 :: "r"(saddr), "l"(gptr));
}
__device__ __forceinline__ void cp_commit() {
    asm volatile("cp.async.commit_group;");
}
__device__ __forceinline__ void cp_wait2() {
    asm volatile("cp.async.wait_group 2;");
}
__device__ __forceinline__ void cp_wait0() {
    asm volatile("cp.async.wait_group 0;");
}
__device__ __forceinline__ void ldsm_x4(unsigned* r, unsigned addr) {
    asm volatile("ldmatrix.sync.aligned.m8n8.x4.shared.b16 {%0,%1,%2,%3}, [%4];"
                 : "=r"(r[0]), "=r"(r[1]), "=r"(r[2]), "=r"(r[3]) : "r"(addr));
}
__device__ __forceinline__ void ldsm_x4_t(unsigned* r, unsigned addr) {
    asm volatile("ldmatrix.sync.aligned.m8n8.x4.trans.shared.b16 {%0,%1,%2,%3}, [%4];"
                 : "=r"(r[0]), "=r"(r[1]), "=r"(r[2]), "=r"(r[3]) : "r"(addr));
}
__device__ __forceinline__ void mma16816(float* c, const unsigned* a, const unsigned* b) {
    asm volatile(
        "mma.sync.aligned.m16n8k16.row.col.f32.f16.f16.f32 "
        "{%0,%1,%2,%3}, {%4,%5,%6,%7}, {%8,%9}, {%0,%1,%2,%3};"
        : "+f"(c[0]), "+f"(c[1]), "+f"(c[2]), "+f"(c[3])
        : "r"(a[0]), "r"(a[1]), "r"(a[2]), "r"(a[3]), "r"(b[0]), "r"(b[1]));
}
__device__ __forceinline__ unsigned packh2(__half a, __half b) {
    __half2 t = __halves2half2(a, b);
    return *(unsigned*)&t;
}
__device__ __forceinline__ unsigned packf2h2(float a, float b) {
    __half2 t = __floats2half2_rn(a, b);
    return *(unsigned*)&t;
}

// ---------------------------------------------------------------------------
// Fused pack: pure fp32 -> fp16 identity convert for 7 arrays.
// ---------------------------------------------------------------------------
__global__ __launch_bounds__(256) void pack_all_kernel(
    const float* __restrict__ A0, const float* __restrict__ A1,
    const float* __restrict__ A2,
    const float* __restrict__ W0, const float* __restrict__ W1,
    const float* __restrict__ W2, const float* __restrict__ W3,
    __half* __restrict__ OA0, __half* __restrict__ OA1, __half* __restrict__ OA2,
    __half* __restrict__ OW0, __half* __restrict__ OW1,
    __half* __restrict__ OW2, __half* __restrict__ OW3)
{
    const int z = blockIdx.y;
    const float* src;
    __half* dst;
    int n4;
    switch (z) {
        case 0: src = A0; dst = OA0; n4 = 393216; break;
        case 1: src = A1; dst = OA1; n4 = 393216; break;
        case 2: src = A2; dst = OA2; n4 = 393216; break;
        case 3: src = W0; dst = OW0; n4 = 147456; break;
        case 4: src = W1; dst = OW1; n4 = 147456; break;
        case 5: src = W2; dst = OW2; n4 = 147456; break;
        default: src = W3; dst = OW3; n4 = 147456; break;
    }
    int g = blockIdx.x * 256 + threadIdx.x;
    if (g >= n4) return;
    float4 v = *(const float4*)&src[g * 4];
    uint2 hw = make_uint2(packh2(__float2half(v.x), __float2half(v.y)),
                          packh2(__float2half(v.z), __float2half(v.w)));
    *(uint2*)&dst[g * 4] = hw;
}

// ---------------------------------------------------------------------------
// HMMA fp16 GEMM: CTA tile 64x128, 8 warps (2x4 -> warp tile 32x32),
// K-chunk 64, 4-stage cp.async pipeline (prefetch distance 3).
// A row-major [m][k]; W row-major [k][n] via ldmatrix.trans. fp32 accum.
// ---------------------------------------------------------------------------
#define A_BYTES 8192                // 64 rows x 128B
#define B_BYTES 16384               // 64 k-rows x 256B
#define STG_B (A_BYTES + B_BYTES)   // 24576

template<bool OUT_HALF>
__global__ __launch_bounds__(256, 2) void gemm_mma_kernel(
    const __half* __restrict__ a0, const __half* __restrict__ a1,
    const __half* __restrict__ a2,
    const __half* __restrict__ b0, const __half* __restrict__ b1,
    const __half* __restrict__ b2,
    const float* __restrict__ bias0, const float* __restrict__ bias1,
    const float* __restrict__ bias2,
    float* __restrict__ cf0, float* __restrict__ cf1, float* __restrict__ cf2,
    __half* __restrict__ ch0, __half* __restrict__ ch1, __half* __restrict__ ch2)
{
    const int z = blockIdx.z;
    const __half* Ah = (z == 0) ? a0 : (z == 1) ? a1 : a2;
    const __half* Wh = (z == 0) ? b0 : (z == 1) ? b1 : b2;
    const float* bias = (z == 0) ? bias0 : (z == 1) ? bias1 : bias2;
    float* Cf = (z == 0) ? cf0 : (z == 1) ? cf1 : cf2;
    __half* Ch = (z == 0) ? ch0 : (z == 1) ? ch1 : ch2;

    extern __shared__ char smem[];
    const unsigned sb = smem_u32(smem);

    const int tid  = threadIdx.x;
    const int wid  = tid >> 5;
    const int lane = tid & 31;
    const int wm   = wid & 1;                   // 2 warp rows x 32
    const int wn   = wid >> 1;                  // 4 warp cols x 32
    const int mBase = blockIdx.y * 64;
    const int nBase = blockIdx.x * 128;

    const __half* aSrc = Ah + (size_t)mBase * GK;

    auto load_stage = [&](int stage, int chunk) {
        unsigned sA = sb + stage * STG_B;
        unsigned sB = sA + A_BYTES;
        // A tile: 64 rows x 8 chunks = 512
#pragma unroll
        for (int it = 0; it < 2; it++) {
            int idx = it * 256 + tid;
            int r = idx >> 3, c = idx & 7;
            cp_async16(sA + r * 128 + ((c ^ (r & 7)) << 4),
                       aSrc + (size_t)r * GK + chunk * CHUNK_K + c * 8);
        }
        // B tile: W[k0:k0+64][nBase:nBase+128] -> 64 rows x 16 chunks = 1024
        const __half* bSrc = Wh + (size_t)chunk * CHUNK_K * D_MOD + nBase;
#pragma unroll
        for (int it = 0; it < 4; it++) {
            int idx = it * 256 + tid;
            int r = idx >> 4;                   // 0..63
            int c16 = idx & 15;
            unsigned off = r * 256 + ((c16 >> 3) << 7)
                         + (((c16 & 7) ^ (r & 7)) << 4);
            cp_async16(sB + off, bSrc + (size_t)r * D_MOD + c16 * 8);
        }
    };

    float acc[2][4][4];
#pragma unroll
    for (int i = 0; i < 2; i++)
#pragma unroll
        for (int j = 0; j < 4; j++)
#pragma unroll
            for (int r = 0; r < 4; r++) acc[i][j][r] = 0.f;

    load_stage(0, 0); cp_commit();
    load_stage(1, 1); cp_commit();
    load_stage(2, 2); cp_commit();

    const int arow_l = wm * 32 + (lane & 15);
    const int asel   = lane >> 4;
    const int brow_l = lane & 15;               // k-row within 16
    const int bsel   = lane >> 4;

    for (int c = 0; c < NCHUNK; c++) {
        cp_wait2();
        __syncthreads();
        if (c + 3 < NCHUNK) { load_stage((c + 3) % GSTAGES, c + 3); cp_commit(); }
        else                { cp_commit(); }

        unsigned sA = sb + (c % GSTAGES) * STG_B;
        unsigned sB = sA + A_BYTES;

#pragma unroll
        for (int ks = 0; ks < 4; ks++) {
            unsigned bfr[2][4];
#pragma unroll
            for (int g = 0; g < 2; g++) {
                int row = ks * 16 + brow_l;
                int cn = wn * 4 + 2 * g + bsel;
                ldsm_x4_t(bfr[g], sB + row * 256 + ((cn >> 3) << 7)
                                   + (((cn & 7) ^ (row & 7)) << 4));
            }
            unsigned afr[2][4];
#pragma unroll
            for (int i = 0; i < 2; i++) {
                int row = arow_l + i * 16;
                int ch = 2 * ks + asel;
                ldsm_x4(afr[i], sA + row * 128 + ((ch ^ (row & 7)) << 4));
            }
#pragma unroll
            for (int i = 0; i < 2; i++) {
#pragma unroll
                for (int g = 0; g < 2; g++) {
                    mma16816(acc[i][2 * g],     afr[i], &bfr[g][0]);
                    mma16816(acc[i][2 * g + 1], afr[i], &bfr[g][2]);
                }
            }
        }
    }

#pragma unroll
    for (int i = 0; i < 2; i++) {
        int row = mBase + wm * 32 + i * 16 + (lane >> 2);
#pragma unroll
        for (int j = 0; j < 4; j++) {
            int col = nBase + wn * 32 + j * 8 + (lane & 3) * 2;
            float2 b2 = *(const float2*)&bias[col];
            if (OUT_HALF) {
                *(__half2*)&Ch[(size_t)row * D_MOD + col] =
                    __floats2half2_rn(acc[i][j][0] + b2.x, acc[i][j][1] + b2.y);
                *(__half2*)&Ch[(size_t)(row + 8) * D_MOD + col] =
                    __floats2half2_rn(acc[i][j][2] + b2.x, acc[i][j][3] + b2.y);
            } else {
                float2 o0 = make_float2(acc[i][j][0] + b2.x, acc[i][j][1] + b2.y);
                float2 o1 = make_float2(acc[i][j][2] + b2.x, acc[i][j][3] + b2.y);
                *(float2*)&Cf[(size_t)row * D_MOD + col] = o0;
                *(float2*)&Cf[(size_t)(row + 8) * D_MOD + col] = o1;
            }
        }
    }
}

// ---------------------------------------------------------------------------
// HMMA sliding-window attention (unchanged: ~11us)
// ---------------------------------------------------------------------------
#define ATTN_SMEM (8192 + 24576 + 24576)

__global__ __launch_bounds__(128) void attn_kernel(
    const __half* __restrict__ Qh, const __half* __restrict__ Kh,
    const __half* __restrict__ Vh, __half* __restrict__ Ch)
{
    extern __shared__ char smraw[];
    const unsigned sb = smem_u32(smraw);
    const unsigned sQ = sb;
    const unsigned sK = sb + 8192;
    const unsigned sV = sb + 8192 + 24576;

    const int qt = blockIdx.x;
    const int h  = blockIdx.y;
    const int qbase = qt * QT;
    const int kbase = qbase - 64;
    const int col0 = h * HDIM;
    const int tid = threadIdx.x;
    const int lane = tid & 31;
    const int w = tid >> 5;

#pragma unroll
    for (int it = 0; it < 4; it++) {
        int idx = it * 128 + tid;
        int r = idx >> 3, c = idx & 7;
        cp_async16(sQ + r * 128 + ((c ^ (r & 7)) << 4),
                   Qh + (size_t)(qbase + r) * D_MOD + col0 + c * 8);
    }
#pragma unroll
    for (int it = 0; it < 12; it++) {
        int idx = it * 128 + tid;
        int j = idx >> 3, c = idx & 7;
        int kj = min(max(kbase + j, 0), S_LEN - 1);
        cp_async16(sK + j * 128 + ((c ^ (j & 7)) << 4),
                   Kh + (size_t)kj * D_MOD + col0 + c * 8);
    }
#pragma unroll
    for (int it = 0; it < 12; it++) {
        int idx = it * 128 + tid;
        int j = idx >> 3, c = idx & 7;
        int kj = min(max(kbase + j, 0), S_LEN - 1);
        cp_async16(sV + j * 128 + ((c ^ (j & 7)) << 4),
                   Vh + (size_t)kj * D_MOD + col0 + c * 8);
    }
    cp_commit();
    cp_wait0();
    __syncthreads();

    const int m0 = w * 16;
    float st[24][4];
#pragma unroll
    for (int t = 0; t < 24; t++)
#pragma unroll
        for (int r = 0; r < 4; r++) st[t][r] = 0.f;

#pragma unroll
    for (int s = 0; s < 4; s++) {
        unsigned afr[4];
        {
            int row = m0 + (lane & 15);
            int ch = 2 * s + (lane >> 4);
            ldsm_x4(afr, sQ + row * 128 + ((ch ^ (row & 7)) << 4));
        }
#pragma unroll
        for (int nt = 0; nt < 12; nt++) {
            unsigned bfr[4];
            int row = nt * 16 + ((lane & 16) ? 8 : 0) + (lane & 7);
            int ch = 2 * s + ((lane >> 3) & 1);
            ldsm_x4(bfr, sK + row * 128 + ((ch ^ (row & 7)) << 4));
            mma16816(st[2 * nt],     afr, &bfr[0]);
            mma16816(st[2 * nt + 1], afr, &bfr[2]);
        }
    }

    const int r0 = m0 + (lane >> 2);
    const int r1 = r0 + 8;
    const int cj = (lane & 3) * 2;

    float mx0 = -1e30f, mx1 = -1e30f;
#pragma unroll
    for (int t = 0; t < 24; t++) {
        int j0 = 8 * t + cj, j1 = j0 + 1;
        bool in0 = ((unsigned)(kbase + j0) < (unsigned)S_LEN);
        bool in1 = ((unsigned)(kbase + j1) < (unsigned)S_LEN);
        st[t][0] = (in0 && (unsigned)(j0 - r0) <= 128u) ? st[t][0] * 0.125f : -1e30f;
        st[t][1] = (in1 && (unsigned)(j1 - r0) <= 128u) ? st[t][1] * 0.125f : -1e30f;
        st[t][2] = (in0 && (unsigned)(j0 - r1) <= 128u) ? st[t][2] * 0.125f : -1e30f;
        st[t][3] = (in1 && (unsigned)(j1 - r1) <= 128u) ? st[t][3] * 0.125f : -1e30f;
        mx0 = fmaxf(mx0, fmaxf(st[t][0], st[t][1]));
        mx1 = fmaxf(mx1, fmaxf(st[t][2], st[t][3]));
    }
    mx0 = fmaxf(mx0, __shfl_xor_sync(0xffffffffu, mx0, 1));
    mx0 = fmaxf(mx0, __shfl_xor_sync(0xffffffffu, mx0, 2));
    mx1 = fmaxf(mx1, __shfl_xor_sync(0xffffffffu, mx1, 1));
    mx1 = fmaxf(mx1, __shfl_xor_sync(0xffffffffu, mx1, 2));

    float l0 = 0.f, l1 = 0.f;
#pragma unroll
    for (int t = 0; t < 24; t++) {
        st[t][0] = __expf(st[t][0] - mx0);
        st[t][1] = __expf(st[t][1] - mx0);
        st[t][2] = __expf(st[t][2] - mx1);
        st[t][3] = __expf(st[t][3] - mx1);
        l0 += st[t][0] + st[t][1];
        l1 += st[t][2] + st[t][3];
    }
    l0 += __shfl_xor_sync(0xffffffffu, l0, 1);
    l0 += __shfl_xor_sync(0xffffffffu, l0, 2);
    l1 += __shfl_xor_sync(0xffffffffu, l1, 1);
    l1 += __shfl_xor_sync(0xffffffffu, l1, 2);
    const float inv0 = 1.0f / l0, inv1 = 1.0f / l1;
#pragma unroll
    for (int t = 0; t < 24; t++) {
        st[t][0] *= inv0; st[t][1] *= inv0;
        st[t][2] *= inv1; st[t][3] *= inv1;
    }

    float o[8][4];
#pragma unroll
    for (int g = 0; g < 8; g++)
#pragma unroll
        for (int r = 0; r < 4; r++) o[g][r] = 0.f;

#pragma unroll
    for (int kk = 0; kk < 12; kk++) {
        unsigned a[4];
        a[0] = packf2h2(st[2 * kk][0],     st[2 * kk][1]);
        a[1] = packf2h2(st[2 * kk][2],     st[2 * kk][3]);
        a[2] = packf2h2(st[2 * kk + 1][0], st[2 * kk + 1][1]);
        a[3] = packf2h2(st[2 * kk + 1][2], st[2 * kk + 1][3]);
        int row = kk * 16 + (lane & 15);
#pragma unroll
        for (int g = 0; g < 4; g++) {
            unsigned bfr[4];
            int ch = 2 * g + (lane >> 4);
            ldsm_x4_t(bfr, sV + row * 128 + ((ch ^ (row & 7)) << 4));
            mma16816(o[2 * g],     a, &bfr[0]);
            mma16816(o[2 * g + 1], a, &bfr[2]);
        }
    }

#pragma unroll
    for (int g = 0; g < 8; g++) {
        int d = col0 + 8 * g + cj;
        *(__half2*)&Ch[(size_t)(qbase + r0) * D_MOD + d] =
            __floats2half2_rn(o[g][0], o[g][1]);
        *(__half2*)&Ch[(size_t)(qbase + r1) * D_MOD + d] =
            __floats2half2_rn(o[g][2], o[g][3]);
    }
}

// ---------------------------------------------------------------------------
extern "C" void kernel_launch(void* const* d_in, const int* in_sizes, int n_in,
                              void* d_out, int out_size) {
    const float* query = (const float*)d_in[0];
    const float* key   = (const float*)d_in[1];
    const float* value = (const float*)d_in[2];
    const float* Wq = (const float*)d_in[3];
    const float* bq = (const float*)d_in[4];
    const float* Wk = (const float*)d_in[5];
    const float* bk = (const float*)d_in[6];
    const float* Wv = (const float*)d_in[7];
    const float* bv = (const float*)d_in[8];
    const float* Wo = (const float*)d_in[9];
    const float* bo = (const float*)d_in[10];
    float* out = (float*)d_out;

    __half *qh, *kh, *vh, *ch, *ah, *wh;
    cudaGetSymbolAddress((void**)&qh, g_Qh);
    cudaGetSymbolAddress((void**)&kh, g_Kh);
    cudaGetSymbolAddress((void**)&vh, g_Vh);
    cudaGetSymbolAddress((void**)&ch, g_Ch);
    cudaGetSymbolAddress((void**)&ah, g_Ah);
    cudaGetSymbolAddress((void**)&wh, g_Wh);
    __half* ah0 = ah;
    __half* ah1 = ah + (size_t)S_LEN * D_MOD;
    __half* ah2 = ah + (size_t)2 * S_LEN * D_MOD;
    __half* wh0 = wh;
    __half* wh1 = wh + (size_t)D_MOD * D_MOD;
    __half* wh2 = wh + (size_t)2 * D_MOD * D_MOD;
    __half* wh3 = wh + (size_t)3 * D_MOD * D_MOD;

    const int gemm_smem = GSTAGES * STG_B;   // 98304
    cudaFuncSetAttribute((const void*)gemm_mma_kernel<true>,
                         cudaFuncAttributeMaxDynamicSharedMemorySize, gemm_smem);
    cudaFuncSetAttribute((const void*)gemm_mma_kernel<false>,
                         cudaFuncAttributeMaxDynamicSharedMemorySize, gemm_smem);
    cudaFuncSetAttribute(attn_kernel,
                         cudaFuncAttributeMaxDynamicSharedMemorySize, ATTN_SMEM);

    // ---- fused pack (all 7 arrays, one launch) ----
    pack_all_kernel<<<dim3(1536, 7), 256>>>(query, key, value, Wq, Wk, Wv, Wo,
                                            ah0, ah1, ah2, wh0, wh1, wh2, wh3);

    // ---- fused Q/K/V projections (fp16 out): 64x128 tiles, 576 CTAs ----
    gemm_mma_kernel<true><<<dim3(6, 32, 3), 256, gemm_smem>>>(
        ah0, ah1, ah2, wh0, wh1, wh2, bq, bk, bv,
        (float*)nullptr, (float*)nullptr, (float*)nullptr, qh, kh, vh);

    // ---- attention (fp16 in/out, HMMA) ----
    attn_kernel<<<dim3(S_LEN / QT, N_HEADS), 128, ATTN_SMEM>>>(qh, kh, vh, ch);

    // ---- output projection (fp32 out): 192 CTAs ----
    gemm_mma_kernel<false><<<dim3(6, 32, 1), 256, gemm_smem>>>(
        ch, ch, ch, wh3, wh3, wh3, bo, bo, bo,
        out, out, out, (__half*)nullptr, (__half*)nullptr, (__half*)nullptr);
}

// round 15
// speedup vs baseline: 1.0706x; 1.0706x over previous
#include <cuda_runtime.h>
#include <cuda_fp16.h>
#include <math.h>

// ---------------- Problem constants ----------------
#define S_LEN 2048
#define D_MOD 768
#define N_HEADS 12
#define HDIM 64
#define QT 64
#define KW 192

// ---------------- fp16 GEMM constants ----------------
#define GK 768
#define NCHUNK 12          // GK / 64
#define CHUNK_K 64

// ---------------- Scratch (no cudaMalloc allowed) ----------------
__device__ __align__(1024) __half g_Qh[S_LEN * D_MOD];
__device__ __align__(1024) __half g_Kh[S_LEN * D_MOD];
__device__ __align__(1024) __half g_Vh[S_LEN * D_MOD];
__device__ __align__(1024) __half g_Ch[S_LEN * D_MOD];
__device__ __align__(1024) __half g_Ah[3][S_LEN * D_MOD];   // fp16 activations
__device__ __align__(1024) __half g_Wh[4][D_MOD * D_MOD];   // fp16 weights [k][n]

// ---------------- PTX helpers (base sm_103-safe: sm_80 era) ----------------
__device__ __forceinline__ unsigned smem_u32(const void* p) {
    unsigned a;
    asm("{ .reg .u64 t; cvta.to.shared.u64 t, %1; cvt.u32.u64 %0, t; }"
        : "=r"(a) : "l"(p));
    return a;
}
__device__ __forceinline__ void cp_async16(unsigned saddr, const void* gptr) {
    asm volatile("cp.async.cg.shared.global [%0], [%1], 16;"
                 :: "r"(saddr), "l"(gptr));
}
__device__ __forceinline__ void cp_commit() {
    asm volatile("cp.async.commit_group;");
}
__device__ __forceinline__ void cp_wait1() {
    asm volatile("cp.async.wait_group 1;");
}
__device__ __forceinline__ void cp_wait2() {
    asm volatile("cp.async.wait_group 2;");
}
__device__ __forceinline__ void cp_wait0() {
    asm volatile("cp.async.wait_group 0;");
}
__device__ __forceinline__ void ldsm_x4(unsigned* r, unsigned addr) {
    asm volatile("ldmatrix.sync.aligned.m8n8.x4.shared.b16 {%0,%1,%2,%3}, [%4];"
                 : "=r"(r[0]), "=r"(r[1]), "=r"(r[2]), "=r"(r[3]) : "r"(addr));
}
__device__ __forceinline__ void ldsm_x4_t(unsigned* r, unsigned addr) {
    asm volatile("ldmatrix.sync.aligned.m8n8.x4.trans.shared.b16 {%0,%1,%2,%3}, [%4];"
                 : "=r"(r[0]), "=r"(r[1]), "=r"(r[2]), "=r"(r[3]) : "r"(addr));
}
__device__ __forceinline__ void mma16816(float* c, const unsigned* a, const unsigned* b) {
    asm volatile(
        "mma.sync.aligned.m16n8k16.row.col.f32.f16.f16.f32 "
        "{%0,%1,%2,%3}, {%4,%5,%6,%7}, {%8,%9}, {%0,%1,%2,%3};"
        : "+f"(c[0]), "+f"(c[1]), "+f"(c[2]), "+f"(c[3])
        : "r"(a[0]), "r"(a[1]), "r"(a[2]), "r"(a[3]), "r"(b[0]), "r"(b[1]));
}
__device__ __forceinline__ unsigned packh2(__half a, __half b) {
    __half2 t = __halves2half2(a, b);
    return *(unsigned*)&t;
}
__device__ __forceinline__ unsigned packf2h2(float a, float b) {
    __half2 t = __floats2half2_rn(a, b);
    return *(unsigned*)&t;
}

// ---------------------------------------------------------------------------
// Fused pack: pure fp32 -> fp16 identity convert for 7 arrays.
// ---------------------------------------------------------------------------
__global__ __launch_bounds__(256) void pack_all_kernel(
    const float* __restrict__ A0, const float* __restrict__ A1,
    const float* __restrict__ A2,
    const float* __restrict__ W0, const float* __restrict__ W1,
    const float* __restrict__ W2, const float* __restrict__ W3,
    __half* __restrict__ OA0, __half* __restrict__ OA1, __half* __restrict__ OA2,
    __half* __restrict__ OW0, __half* __restrict__ OW1,
    __half* __restrict__ OW2, __half* __restrict__ OW3)
{
    const int z = blockIdx.y;
    const float* src;
    __half* dst;
    int n4;
    switch (z) {
        case 0: src = A0; dst = OA0; n4 = 393216; break;
        case 1: src = A1; dst = OA1; n4 = 393216; break;
        case 2: src = A2; dst = OA2; n4 = 393216; break;
        case 3: src = W0; dst = OW0; n4 = 147456; break;
        case 4: src = W1; dst = OW1; n4 = 147456; break;
        case 5: src = W2; dst = OW2; n4 = 147456; break;
        default: src = W3; dst = OW3; n4 = 147456; break;
    }
    int g = blockIdx.x * 256 + threadIdx.x;
    if (g >= n4) return;
    float4 v = *(const float4*)&src[g * 4];
    uint2 hw = make_uint2(packh2(__float2half(v.x), __float2half(v.y)),
                          packh2(__float2half(v.z), __float2half(v.w)));
    *(uint2*)&dst[g * 4] = hw;
}

// ---------------------------------------------------------------------------
// HMMA fp16 GEMM: CTA tile 128x128, 8 warps (2x4 -> warp tile 64x32),
// K-chunk 64, STAGES-deep cp.async pipeline (prefetch distance STAGES-1).
// A row-major [m][k]; W row-major [k][n] via ldmatrix.trans. fp32 accum.
// Stage = A 16KB + B 16KB = 32KB.
// ---------------------------------------------------------------------------
#define A_BYTES 16384               // 128 rows x 128B
#define B_BYTES 16384               // 64 k-rows x 256B
#define STG_B (A_BYTES + B_BYTES)   // 32768

template<int STAGES, bool OUT_HALF>
__global__ __launch_bounds__(256, 2) void gemm_mma_kernel(
    const __half* __restrict__ a0, const __half* __restrict__ a1,
    const __half* __restrict__ a2,
    const __half* __restrict__ b0, const __half* __restrict__ b1,
    const __half* __restrict__ b2,
    const float* __restrict__ bias0, const float* __restrict__ bias1,
    const float* __restrict__ bias2,
    float* __restrict__ cf0, float* __restrict__ cf1, float* __restrict__ cf2,
    __half* __restrict__ ch0, __half* __restrict__ ch1, __half* __restrict__ ch2)
{
    const int z = blockIdx.z;
    const __half* Ah = (z == 0) ? a0 : (z == 1) ? a1 : a2;
    const __half* Wh = (z == 0) ? b0 : (z == 1) ? b1 : b2;
    const float* bias = (z == 0) ? bias0 : (z == 1) ? bias1 : bias2;
    float* Cf = (z == 0) ? cf0 : (z == 1) ? cf1 : cf2;
    __half* Ch = (z == 0) ? ch0 : (z == 1) ? ch1 : ch2;

    extern __shared__ char smem[];
    const unsigned sb = smem_u32(smem);

    const int tid  = threadIdx.x;
    const int wid  = tid >> 5;
    const int lane = tid & 31;
    const int wm   = wid & 1;                   // 2 warp rows x 64
    const int wn   = wid >> 1;                  // 4 warp cols x 32
    const int mBase = blockIdx.y * 128;
    const int nBase = blockIdx.x * 128;

    const __half* aSrc = Ah + (size_t)mBase * GK;

    auto load_stage = [&](int stage, int chunk) {
        unsigned sA = sb + stage * STG_B;
        unsigned sB = sA + A_BYTES;
        // A tile: 128 rows x 8 chunks = 1024
#pragma unroll
        for (int it = 0; it < 4; it++) {
            int idx = it * 256 + tid;
            int r = idx >> 3, c = idx & 7;
            cp_async16(sA + r * 128 + ((c ^ (r & 7)) << 4),
                       aSrc + (size_t)r * GK + chunk * CHUNK_K + c * 8);
        }
        // B tile: W[k0:k0+64][nBase:nBase+128] -> 64 rows x 16 chunks = 1024
        const __half* bSrc = Wh + (size_t)chunk * CHUNK_K * D_MOD + nBase;
#pragma unroll
        for (int it = 0; it < 4; it++) {
            int idx = it * 256 + tid;
            int r = idx >> 4;                   // 0..63
            int c16 = idx & 15;
            unsigned off = r * 256 + ((c16 >> 3) << 7)
                         + (((c16 & 7) ^ (r & 7)) << 4);
            cp_async16(sB + off, bSrc + (size_t)r * D_MOD + c16 * 8);
        }
    };

    float acc[4][4][4];
#pragma unroll
    for (int i = 0; i < 4; i++)
#pragma unroll
        for (int j = 0; j < 4; j++)
#pragma unroll
            for (int r = 0; r < 4; r++) acc[i][j][r] = 0.f;

#pragma unroll
    for (int s = 0; s < STAGES - 1; s++) {
        load_stage(s, s);
        cp_commit();
    }

    const int arow_l = wm * 64 + (lane & 15);
    const int asel   = lane >> 4;
    const int brow_l = lane & 15;               // k-row within 16
    const int bsel   = lane >> 4;

    for (int c = 0; c < NCHUNK; c++) {
        if (STAGES == 3) cp_wait1(); else cp_wait2();
        __syncthreads();
        if (c + STAGES - 1 < NCHUNK) {
            load_stage((c + STAGES - 1) % STAGES, c + STAGES - 1);
            cp_commit();
        } else {
            cp_commit();
        }

        unsigned sA = sb + (c % STAGES) * STG_B;
        unsigned sB = sA + A_BYTES;

#pragma unroll
        for (int ks = 0; ks < 4; ks++) {
            unsigned bfr[2][4];
#pragma unroll
            for (int g = 0; g < 2; g++) {
                int row = ks * 16 + brow_l;
                int cn = wn * 4 + 2 * g + bsel;
                ldsm_x4_t(bfr[g], sB + row * 256 + ((cn >> 3) << 7)
                                   + (((cn & 7) ^ (row & 7)) << 4));
            }
            unsigned afr[4][4];
#pragma unroll
            for (int i = 0; i < 4; i++) {
                int row = arow_l + i * 16;
                int ch = 2 * ks + asel;
                ldsm_x4(afr[i], sA + row * 128 + ((ch ^ (row & 7)) << 4));
            }
#pragma unroll
            for (int i = 0; i < 4; i++) {
#pragma unroll
                for (int g = 0; g < 2; g++) {
                    mma16816(acc[i][2 * g],     afr[i], &bfr[g][0]);
                    mma16816(acc[i][2 * g + 1], afr[i], &bfr[g][2]);
                }
            }
        }
    }

#pragma unroll
    for (int i = 0; i < 4; i++) {
        int row = mBase + wm * 64 + i * 16 + (lane >> 2);
#pragma unroll
        for (int j = 0; j < 4; j++) {
            int col = nBase + wn * 32 + j * 8 + (lane & 3) * 2;
            float2 b2 = *(const float2*)&bias[col];
            if (OUT_HALF) {
                *(__half2*)&Ch[(size_t)row * D_MOD + col] =
                    __floats2half2_rn(acc[i][j][0] + b2.x, acc[i][j][1] + b2.y);
                *(__half2*)&Ch[(size_t)(row + 8) * D_MOD + col] =
                    __floats2half2_rn(acc[i][j][2] + b2.x, acc[i][j][3] + b2.y);
            } else {
                float2 o0 = make_float2(acc[i][j][0] + b2.x, acc[i][j][1] + b2.y);
                float2 o1 = make_float2(acc[i][j][2] + b2.x, acc[i][j][3] + b2.y);
                *(float2*)&Cf[(size_t)row * D_MOD + col] = o0;
                *(float2*)&Cf[(size_t)(row + 8) * D_MOD + col] = o1;
            }
        }
    }
}

// ---------------------------------------------------------------------------
// HMMA sliding-window attention (unchanged: ~11us)
// ---------------------------------------------------------------------------
#define ATTN_SMEM (8192 + 24576 + 24576)

__global__ __launch_bounds__(128) void attn_kernel(
    const __half* __restrict__ Qh, const __half* __restrict__ Kh,
    const __half* __restrict__ Vh, __half* __restrict__ Ch)
{
    extern __shared__ char smraw[];
    const unsigned sb = smem_u32(smraw);
    const unsigned sQ = sb;
    const unsigned sK = sb + 8192;
    const unsigned sV = sb + 8192 + 24576;

    const int qt = blockIdx.x;
    const int h  = blockIdx.y;
    const int qbase = qt * QT;
    const int kbase = qbase - 64;
    const int col0 = h * HDIM;
    const int tid = threadIdx.x;
    const int lane = tid & 31;
    const int w = tid >> 5;

#pragma unroll
    for (int it = 0; it < 4; it++) {
        int idx = it * 128 + tid;
        int r = idx >> 3, c = idx & 7;
        cp_async16(sQ + r * 128 + ((c ^ (r & 7)) << 4),
                   Qh + (size_t)(qbase + r) * D_MOD + col0 + c * 8);
    }
#pragma unroll
    for (int it = 0; it < 12; it++) {
        int idx = it * 128 + tid;
        int j = idx >> 3, c = idx & 7;
        int kj = min(max(kbase + j, 0), S_LEN - 1);
        cp_async16(sK + j * 128 + ((c ^ (j & 7)) << 4),
                   Kh + (size_t)kj * D_MOD + col0 + c * 8);
    }
#pragma unroll
    for (int it = 0; it < 12; it++) {
        int idx = it * 128 + tid;
        int j = idx >> 3, c = idx & 7;
        int kj = min(max(kbase + j, 0), S_LEN - 1);
        cp_async16(sV + j * 128 + ((c ^ (j & 7)) << 4),
                   Vh + (size_t)kj * D_MOD + col0 + c * 8);
    }
    cp_commit();
    cp_wait0();
    __syncthreads();

    const int m0 = w * 16;
    float st[24][4];
#pragma unroll
    for (int t = 0; t < 24; t++)
#pragma unroll
        for (int r = 0; r < 4; r++) st[t][r] = 0.f;

#pragma unroll
    for (int s = 0; s < 4; s++) {
        unsigned afr[4];
        {
            int row = m0 + (lane & 15);
            int ch = 2 * s + (lane >> 4);
            ldsm_x4(afr, sQ + row * 128 + ((ch ^ (row & 7)) << 4));
        }
#pragma unroll
        for (int nt = 0; nt < 12; nt++) {
            unsigned bfr[4];
            int row = nt * 16 + ((lane & 16) ? 8 : 0) + (lane & 7);
            int ch = 2 * s + ((lane >> 3) & 1);
            ldsm_x4(bfr, sK + row * 128 + ((ch ^ (row & 7)) << 4));
            mma16816(st[2 * nt],     afr, &bfr[0]);
            mma16816(st[2 * nt + 1], afr, &bfr[2]);
        }
    }

    const int r0 = m0 + (lane >> 2);
    const int r1 = r0 + 8;
    const int cj = (lane & 3) * 2;

    float mx0 = -1e30f, mx1 = -1e30f;
#pragma unroll
    for (int t = 0; t < 24; t++) {
        int j0 = 8 * t + cj, j1 = j0 + 1;
        bool in0 = ((unsigned)(kbase + j0) < (unsigned)S_LEN);
        bool in1 = ((unsigned)(kbase + j1) < (unsigned)S_LEN);
        st[t][0] = (in0 && (unsigned)(j0 - r0) <= 128u) ? st[t][0] * 0.125f : -1e30f;
        st[t][1] = (in1 && (unsigned)(j1 - r0) <= 128u) ? st[t][1] * 0.125f : -1e30f;
        st[t][2] = (in0 && (unsigned)(j0 - r1) <= 128u) ? st[t][2] * 0.125f : -1e30f;
        st[t][3] = (in1 && (unsigned)(j1 - r1) <= 128u) ? st[t][3] * 0.125f : -1e30f;
        mx0 = fmaxf(mx0, fmaxf(st[t][0], st[t][1]));
        mx1 = fmaxf(mx1, fmaxf(st[t][2], st[t][3]));
    }
    mx0 = fmaxf(mx0, __shfl_xor_sync(0xffffffffu, mx0, 1));
    mx0 = fmaxf(mx0, __shfl_xor_sync(0xffffffffu, mx0, 2));
    mx1 = fmaxf(mx1, __shfl_xor_sync(0xffffffffu, mx1, 1));
    mx1 = fmaxf(mx1, __shfl_xor_sync(0xffffffffu, mx1, 2));

    float l0 = 0.f, l1 = 0.f;
#pragma unroll
    for (int t = 0; t < 24; t++) {
        st[t][0] = __expf(st[t][0] - mx0);
        st[t][1] = __expf(st[t][1] - mx0);
        st[t][2] = __expf(st[t][2] - mx1);
        st[t][3] = __expf(st[t][3] - mx1);
        l0 += st[t][0] + st[t][1];
        l1 += st[t][2] + st[t][3];
    }
    l0 += __shfl_xor_sync(0xffffffffu, l0, 1);
    l0 += __shfl_xor_sync(0xffffffffu, l0, 2);
    l1 += __shfl_xor_sync(0xffffffffu, l1, 1);
    l1 += __shfl_xor_sync(0xffffffffu, l1, 2);
    const float inv0 = 1.0f / l0, inv1 = 1.0f / l1;
#pragma unroll
    for (int t = 0; t < 24; t++) {
        st[t][0] *= inv0; st[t][1] *= inv0;
        st[t][2] *= inv1; st[t][3] *= inv1;
    }

    float o[8][4];
#pragma unroll
    for (int g = 0; g < 8; g++)
#pragma unroll
        for (int r = 0; r < 4; r++) o[g][r] = 0.f;

#pragma unroll
    for (int kk = 0; kk < 12; kk++) {
        unsigned a[4];
        a[0] = packf2h2(st[2 * kk][0],     st[2 * kk][1]);
        a[1] = packf2h2(st[2 * kk][2],     st[2 * kk][3]);
        a[2] = packf2h2(st[2 * kk + 1][0], st[2 * kk + 1][1]);
        a[3] = packf2h2(st[2 * kk + 1][2], st[2 * kk + 1][3]);
        int row = kk * 16 + (lane & 15);
#pragma unroll
        for (int g = 0; g < 4; g++) {
            unsigned bfr[4];
            int ch = 2 * g + (lane >> 4);
            ldsm_x4_t(bfr, sV + row * 128 + ((ch ^ (row & 7)) << 4));
            mma16816(o[2 * g],     a, &bfr[0]);
            mma16816(o[2 * g + 1], a, &bfr[2]);
        }
    }

#pragma unroll
    for (int g = 0; g < 8; g++) {
        int d = col0 + 8 * g + cj;
        *(__half2*)&Ch[(size_t)(qbase + r0) * D_MOD + d] =
            __floats2half2_rn(o[g][0], o[g][1]);
        *(__half2*)&Ch[(size_t)(qbase + r1) * D_MOD + d] =
            __floats2half2_rn(o[g][2], o[g][3]);
    }
}

// ---------------------------------------------------------------------------
extern "C" void kernel_launch(void* const* d_in, const int* in_sizes, int n_in,
                              void* d_out, int out_size) {
    const float* query = (const float*)d_in[0];
    const float* key   = (const float*)d_in[1];
    const float* value = (const float*)d_in[2];
    const float* Wq = (const float*)d_in[3];
    const float* bq = (const float*)d_in[4];
    const float* Wk = (const float*)d_in[5];
    const float* bk = (const float*)d_in[6];
    const float* Wv = (const float*)d_in[7];
    const float* bv = (const float*)d_in[8];
    const float* Wo = (const float*)d_in[9];
    const float* bo = (const float*)d_in[10];
    float* out = (float*)d_out;

    __half *qh, *kh, *vh, *ch, *ah, *wh;
    cudaGetSymbolAddress((void**)&qh, g_Qh);
    cudaGetSymbolAddress((void**)&kh, g_Kh);
    cudaGetSymbolAddress((void**)&vh, g_Vh);
    cudaGetSymbolAddress((void**)&ch, g_Ch);
    cudaGetSymbolAddress((void**)&ah, g_Ah);
    cudaGetSymbolAddress((void**)&wh, g_Wh);
    __half* ah0 = ah;
    __half* ah1 = ah + (size_t)S_LEN * D_MOD;
    __half* ah2 = ah + (size_t)2 * S_LEN * D_MOD;
    __half* wh0 = wh;
    __half* wh1 = wh + (size_t)D_MOD * D_MOD;
    __half* wh2 = wh + (size_t)2 * D_MOD * D_MOD;
    __half* wh3 = wh + (size_t)3 * D_MOD * D_MOD;

    const int gemm_smem3 = 3 * STG_B;   // 98304  (QKV: 2 CTAs/SM)
    const int gemm_smem4 = 4 * STG_B;   // 131072 (O: 1 CTA/SM, deeper pipe)
    cudaFuncSetAttribute((const void*)gemm_mma_kernel<3, true>,
                         cudaFuncAttributeMaxDynamicSharedMemorySize, gemm_smem3);
    cudaFuncSetAttribute((const void*)gemm_mma_kernel<4, false>,
                         cudaFuncAttributeMaxDynamicSharedMemorySize, gemm_smem4);
    cudaFuncSetAttribute(attn_kernel,
                         cudaFuncAttributeMaxDynamicSharedMemorySize, ATTN_SMEM);

    // ---- fused pack (all 7 arrays, one launch) ----
    pack_all_kernel<<<dim3(1536, 7), 256>>>(query, key, value, Wq, Wk, Wv, Wo,
                                            ah0, ah1, ah2, wh0, wh1, wh2, wh3);

    // ---- fused Q/K/V projections (fp16 out): 128x128 tiles, 288 CTAs ----
    gemm_mma_kernel<3, true><<<dim3(6, 16, 3), 256, gemm_smem3>>>(
        ah0, ah1, ah2, wh0, wh1, wh2, bq, bk, bv,
        (float*)nullptr, (float*)nullptr, (float*)nullptr, qh, kh, vh);

    // ---- attention (fp16 in/out, HMMA) ----
    attn_kernel<<<dim3(S_LEN / QT, N_HEADS), 128, ATTN_SMEM>>>(qh, kh, vh, ch);

    // ---- output projection (fp32 out): 128x128 tiles, 96 CTAs, 4-stage ----
    gemm_mma_kernel<4, false><<<dim3(6, 16, 1), 256, gemm_smem4>>>(
        ch, ch, ch, wh3, wh3, wh3, bo, bo, bo,
        out, out, out, (__half*)nullptr, (__half*)nullptr, (__half*)nullptr);
}